// round 3
// baseline (speedup 1.0000x reference)
#include <cuda_runtime.h>

// ---------------------------------------------------------------------------
// SimpleYOLOLoss on GB300 — single fused kernel.
// Inputs mapped BY ELEMENT COUNT (robust to metadata ordering):
//   cls_pK : [32, 4, H, W]   H=W in {128,64,32,16}
//   reg_pK : [32, 64, H, W]
//   targets: [32, 64, 5] (cid, x1, y1, x2, y2)
// Output: 4 floats (total, cls_l, box_l, dfl_l)
//
// Accumulators live in __device__ globals (zero at load); the LAST arriving
// block combines, writes the output, and resets everything to zero so each
// graph replay starts from a clean state. No zero/finalize launches.
// ---------------------------------------------------------------------------

#define FULL_MASK 0xffffffffu

static constexpr int BATCH = 32;
static constexpr int NTGT  = 64;

// cls rows (B*H*W) per level: 524288 + 131072 + 32768 + 8192 = 696320 = 2720*256
static constexpr int CLS_BLOCKS = 2720;
static constexpr int TGT_BLOCKS = 1024;   // 8192 warp-items, 8 warps/block
static constexpr int TOTAL_BLOCKS = CLS_BLOCKS + TGT_BLOCKS;

__device__ double       g_S[BATCH];   // per-batch sum over levels of base_lvl[b]
__device__ int          g_cnt[BATCH]; // valid targets per batch
__device__ double       g_adj;
__device__ double       g_box;
__device__ double       g_dfl;
__device__ unsigned int g_arrive;

__global__ void __launch_bounds__(256) yolo_fused_kernel(
    const float* __restrict__ c0, const float* __restrict__ c1,
    const float* __restrict__ c2, const float* __restrict__ c3,
    const float* __restrict__ r0, const float* __restrict__ r1,
    const float* __restrict__ r2, const float* __restrict__ r3,
    const float* __restrict__ tg,
    float* __restrict__ out)
{
    const int tid = threadIdx.x;

    if (blockIdx.x < CLS_BLOCKS) {
        // ------------------- cls base term -------------------
        int row0 = blockIdx.x * 256;
        int lvl_base, HW;
        const float* cp;
        if (row0 < 524288)      { lvl_base = 0;      HW = 16384; cp = c0; }
        else if (row0 < 655360) { lvl_base = 524288; HW = 4096;  cp = c1; }
        else if (row0 < 688128) { lvl_base = 655360; HW = 1024;  cp = c2; }
        else                    { lvl_base = 688128; HW = 256;   cp = c3; }

        int local = row0 - lvl_base;
        int b = local / HW;              // whole block lies in one (level, batch)
        int r = (local - b * HW) + tid;

        const float4 v = *reinterpret_cast<const float4*>(
            cp + ((size_t)b * HW + (size_t)r) * 4);

        float m  = fmaxf(fmaxf(v.x, v.y), fmaxf(v.z, v.w));
        float se = __expf(v.x - m) + __expf(v.y - m) +
                   __expf(v.z - m) + __expf(v.w - m);
        float val = (m + __logf(se)) - v.x;        // lse - logit0

        #pragma unroll
        for (int o = 16; o > 0; o >>= 1)
            val += __shfl_xor_sync(FULL_MASK, val, o);

        __shared__ float wsum[8];
        int wid = tid >> 5;
        if ((tid & 31) == 0) wsum[wid] = val;
        __syncthreads();
        if (tid == 0) {
            double s = 0.0;
            #pragma unroll
            for (int i = 0; i < 8; i++) s += (double)wsum[i];
            atomicAdd(&g_S[b], s / (double)HW);
        }
    } else {
        // ------------------- per-target term -------------------
        __shared__ double s_acc[3];
        __shared__ int    s_cnt;
        if (tid < 3) s_acc[tid] = 0.0;
        if (tid == 3) s_cnt = 0;
        __syncthreads();

        int item = (blockIdx.x - CLS_BLOCKS) * 8 + (tid >> 5);
        int lane = tid & 31;
        int b   = item >> 8;          // constant within a block (8 | 256)
        int rem = item & 255;
        int n   = rem >> 2;
        int lvl = rem & 3;

        const float* tp = tg + (size_t)(b * NTGT + n) * 5;
        float t0 = tp[0];
        if (t0 >= 0.0f) {
            float x1 = tp[1], y1 = tp[2], x2 = tp[3], y2 = tp[4];
            float cx = (x1 + x2) * 0.5f;
            float cy = (y1 + y2) * 0.5f;
            float s  = (float)(8 << lvl);
            int   Wl = 128 >> lvl;
            int   HW = Wl * Wl;

            int gx = (int)(cx / s); gx = min(max(gx, 0), Wl - 1);
            int gy = (int)(cy / s); gy = min(max(gy, 0), Wl - 1);

            const float* cp = (lvl == 0) ? c0 : (lvl == 1) ? c1 : (lvl == 2) ? c2 : c3;
            const float* rp = (lvl == 0) ? r0 : (lvl == 1) ? r1 : (lvl == 2) ? r2 : r3;

            float tr0 = (cx - (float)gx * s) / s;
            float tr1 = (cy - (float)gy * s) / s;
            float tr2 = (x2 - x1) / s;
            float tr3 = (y2 - y1) / s;

            // gather 64 reg channels at the assigned cell: lane -> c=lane, c=lane+32
            const float* rbase = rp + (size_t)b * 64 * HW + (size_t)gy * Wl + gx;
            float p0 = rbase[(size_t)lane * HW];
            float p1 = rbase[(size_t)(lane + 32) * HW];

            float trA = (lane < 16) ? tr0 : tr1;
            float trB = (lane < 16) ? tr2 : tr3;

            // dfl: sum |pred - treg[g]| over all 64
            float d = fabsf(p0 - trA) + fabsf(p1 - trB);
            #pragma unroll
            for (int o = 16; o > 0; o >>= 1)
                d += __shfl_xor_sync(FULL_MASK, d, o);

            // 16-lane segmented sums for per-group means
            float q0 = p0, q1 = p1;
            #pragma unroll
            for (int o = 8; o > 0; o >>= 1) {
                q0 += __shfl_xor_sync(FULL_MASK, q0, o);
                q1 += __shfl_xor_sync(FULL_MASK, q1, o);
            }
            float m1 = __shfl_sync(FULL_MASK, q0, 16);  // group 1 sum
            float m3 = __shfl_sync(FULL_MASK, q1, 16);  // group 3 sum

            if (lane == 0) {
                int cid = (int)fmaxf(t0, 0.0f);
                const float* lptr = cp + ((size_t)b * HW + (size_t)(gy * Wl + gx)) * 4;
                float adj = (lptr[0] - lptr[cid]) / (float)HW;

                const float inv16 = 1.0f / 16.0f;
                float box = (fabsf(q0 * inv16 - tr0) + fabsf(m1 * inv16 - tr1) +
                             fabsf(q1 * inv16 - tr2) + fabsf(m3 * inv16 - tr3)) * 0.25f;
                float dfl = d * (1.0f / 64.0f);

                atomicAdd(&s_acc[0], (double)adj);
                atomicAdd(&s_acc[1], (double)box);
                atomicAdd(&s_acc[2], (double)dfl);
                if (lvl == 0) atomicAdd(&s_cnt, 1);  // count each valid target once
            }
        }
        __syncthreads();
        if (tid == 0) {
            atomicAdd(&g_adj, s_acc[0]);
            atomicAdd(&g_box, s_acc[1]);
            atomicAdd(&g_dfl, s_acc[2]);
            if (s_cnt) atomicAdd(&g_cnt[b], s_cnt);
        }
    }

    // ------------------- last-block finalize + reset -------------------
    __shared__ bool is_last;
    __threadfence();
    if (tid == 0) {
        unsigned int v = atomicAdd(&g_arrive, 1u);
        is_last = (v == (unsigned)(TOTAL_BLOCKS - 1));
    }
    __syncthreads();

    if (is_last) {
        __threadfence();   // acquire: see all other blocks' accumulator writes
        if (tid == 0) {
            double cls = g_adj;
            #pragma unroll
            for (int b = 0; b < BATCH; b++)
                cls += (double)g_cnt[b] * g_S[b];
            float clsf = (float)cls;
            float boxf = (float)g_box;
            float dflf = (float)g_dfl;
            out[0] = 0.3f * clsf + 8.0f * boxf + 1.5f * dflf;
            out[1] = clsf;
            out[2] = boxf;
            out[3] = dflf;
        }
        __syncthreads();   // output computed before anyone resets state
        if (tid < BATCH)     { g_S[tid] = 0.0; g_cnt[tid] = 0; }
        if (tid == BATCH)      g_adj = 0.0;
        if (tid == BATCH + 1)  g_box = 0.0;
        if (tid == BATCH + 2)  g_dfl = 0.0;
        if (tid == BATCH + 3)  g_arrive = 0u;
    }
}

extern "C" void kernel_launch(void* const* d_in, const int* in_sizes, int n_in,
                              void* d_out, int out_size)
{
    // Map inputs by element count (order-agnostic).
    // Unique: reg_p3=33554432, reg_p4=8388608, cls_p5=131072, cls_p6=32768,
    //         targets=10240.
    // Ambiguous pairs resolved by first-occurrence (cls precedes its reg twin
    // in both grouped and interleaved metadata orders):
    //   2097152: first = cls_p3, second = reg_p5
    //   524288 : first = cls_p4, second = reg_p6
    const float *c0 = nullptr, *c1 = nullptr, *c2 = nullptr, *c3 = nullptr;
    const float *r0 = nullptr, *r1 = nullptr, *r2 = nullptr, *r3 = nullptr;
    const float *tg = nullptr;
    int seen2097152 = 0, seen524288 = 0;

    for (int i = 0; i < n_in; i++) {
        const float* p = (const float*)d_in[i];
        switch (in_sizes[i]) {
            case 33554432: r0 = p; break;
            case 8388608:  r1 = p; break;
            case 131072:   c2 = p; break;
            case 32768:    c3 = p; break;
            case 10240:    tg = p; break;
            case 2097152:
                if (seen2097152++ == 0) c0 = p; else r2 = p;
                break;
            case 524288:
                if (seen524288++ == 0) c1 = p; else r3 = p;
                break;
            default: break;
        }
    }

    float* out = (float*)d_out;
    yolo_fused_kernel<<<TOTAL_BLOCKS, 256>>>(c0, c1, c2, c3,
                                             r0, r1, r2, r3, tg, out);
}

// round 4
// speedup vs baseline: 1.3209x; 1.3209x over previous
#include <cuda_runtime.h>

// ---------------------------------------------------------------------------
// SimpleYOLOLoss on GB300 — single fused kernel, high-MLP streaming.
// Inputs mapped BY ELEMENT COUNT (robust to metadata ordering).
//   cls_pK : [32, 4, H, W]   H=W in {128,64,32,16}
//   reg_pK : [32, 64, H, W]
//   targets: [32, 64, 5] (cid, x1, y1, x2, y2)
// Output: 4 floats (total, cls_l, box_l, dfl_l)
// ---------------------------------------------------------------------------

#define FULL_MASK 0xffffffffu

static constexpr int BATCH = 32;
static constexpr int NTGT  = 64;

// Target phase first (long-latency gathers issue early): 8192 warp-items.
static constexpr int TGT_BLOCKS = 1024;
// cls phase: blocks each own a chunk inside one (level, batch).
//   L0: 8 blocks/batch (2048 rows, 8 iters)  -> 256 blocks
//   L1: 2 blocks/batch (2048 rows, 8 iters)  ->  64 blocks
//   L2: 1 block /batch (1024 rows, 4 iters)  ->  32 blocks
//   L3: 1 block /batch ( 256 rows, 1 iter )  ->  32 blocks
static constexpr int CLS_BLOCKS = 256 + 64 + 32 + 32;   // 384
static constexpr int TOTAL_BLOCKS = TGT_BLOCKS + CLS_BLOCKS;

__device__ double       g_S[BATCH];   // per-batch sum over levels of base mean
__device__ int          g_cnt[BATCH]; // valid targets per batch
__device__ double       g_adj;
__device__ double       g_box;
__device__ double       g_dfl;
__device__ unsigned int g_arrive;

__global__ void __launch_bounds__(256) yolo_fused_kernel(
    const float* __restrict__ c0, const float* __restrict__ c1,
    const float* __restrict__ c2, const float* __restrict__ c3,
    const float* __restrict__ r0, const float* __restrict__ r1,
    const float* __restrict__ r2, const float* __restrict__ r3,
    const float* __restrict__ tg,
    float* __restrict__ out)
{
    const int tid = threadIdx.x;

    if (blockIdx.x < TGT_BLOCKS) {
        // ------------------- per-target term -------------------
        __shared__ double s_acc[3];
        __shared__ int    s_cnt;
        if (tid < 3) s_acc[tid] = 0.0;
        if (tid == 3) s_cnt = 0;
        __syncthreads();

        int item = blockIdx.x * 8 + (tid >> 5);
        int lane = tid & 31;
        int b   = item >> 8;          // constant within a block (8 | 256)
        int rem = item & 255;
        int n   = rem >> 2;
        int lvl = rem & 3;

        const float* tp = tg + (size_t)(b * NTGT + n) * 5;
        float t0 = tp[0];
        if (t0 >= 0.0f) {
            float x1 = tp[1], y1 = tp[2], x2 = tp[3], y2 = tp[4];
            float cx = (x1 + x2) * 0.5f;
            float cy = (y1 + y2) * 0.5f;
            float s  = (float)(8 << lvl);
            int   Wl = 128 >> lvl;
            int   HW = Wl * Wl;

            int gx = (int)(cx / s); gx = min(max(gx, 0), Wl - 1);
            int gy = (int)(cy / s); gy = min(max(gy, 0), Wl - 1);

            const float* cp = (lvl == 0) ? c0 : (lvl == 1) ? c1 : (lvl == 2) ? c2 : c3;
            const float* rp = (lvl == 0) ? r0 : (lvl == 1) ? r1 : (lvl == 2) ? r2 : r3;

            float tr0 = (cx - (float)gx * s) / s;
            float tr1 = (cy - (float)gy * s) / s;
            float tr2 = (x2 - x1) / s;
            float tr3 = (y2 - y1) / s;

            // gather 64 reg channels at the assigned cell: lane -> c=lane, c=lane+32
            const float* rbase = rp + (size_t)b * 64 * HW + (size_t)gy * Wl + gx;
            float p0 = rbase[(size_t)lane * HW];
            float p1 = rbase[(size_t)(lane + 32) * HW];

            float trA = (lane < 16) ? tr0 : tr1;
            float trB = (lane < 16) ? tr2 : tr3;

            // dfl: sum |pred - treg[g]| over all 64
            float d = fabsf(p0 - trA) + fabsf(p1 - trB);
            #pragma unroll
            for (int o = 16; o > 0; o >>= 1)
                d += __shfl_xor_sync(FULL_MASK, d, o);

            // 16-lane segmented sums for per-group means
            float q0 = p0, q1 = p1;
            #pragma unroll
            for (int o = 8; o > 0; o >>= 1) {
                q0 += __shfl_xor_sync(FULL_MASK, q0, o);
                q1 += __shfl_xor_sync(FULL_MASK, q1, o);
            }
            float m1 = __shfl_sync(FULL_MASK, q0, 16);  // group 1 sum
            float m3 = __shfl_sync(FULL_MASK, q1, 16);  // group 3 sum

            if (lane == 0) {
                int cid = (int)fmaxf(t0, 0.0f);
                const float* lptr = cp + ((size_t)b * HW + (size_t)(gy * Wl + gx)) * 4;
                float adj = (lptr[0] - lptr[cid]) / (float)HW;

                const float inv16 = 1.0f / 16.0f;
                float box = (fabsf(q0 * inv16 - tr0) + fabsf(m1 * inv16 - tr1) +
                             fabsf(q1 * inv16 - tr2) + fabsf(m3 * inv16 - tr3)) * 0.25f;
                float dfl = d * (1.0f / 64.0f);

                atomicAdd(&s_acc[0], (double)adj);
                atomicAdd(&s_acc[1], (double)box);
                atomicAdd(&s_acc[2], (double)dfl);
                if (lvl == 0) atomicAdd(&s_cnt, 1);  // count each valid target once
            }
        }
        __syncthreads();
        if (tid == 0) {
            atomicAdd(&g_adj, s_acc[0]);
            atomicAdd(&g_box, s_acc[1]);
            atomicAdd(&g_dfl, s_acc[2]);
            if (s_cnt) atomicAdd(&g_cnt[b], s_cnt);
        }
    } else {
        // ------------------- cls base term (high-MLP streaming) -----------
        int cb = blockIdx.x - TGT_BLOCKS;
        const float* cp;
        int b, iters, HW;
        size_t row0;                      // row within this batch's level map
        if (cb < 256)      { cp = c0; HW = 16384; b = cb >> 3;         iters = 8; row0 = (size_t)(cb & 7) * 2048; }
        else if (cb < 320) { cp = c1; HW = 4096;  b = (cb - 256) >> 1; iters = 8; row0 = (size_t)((cb - 256) & 1) * 2048; }
        else if (cb < 352) { cp = c2; HW = 1024;  b = cb - 320;        iters = 4; row0 = 0; }
        else               { cp = c3; HW = 256;   b = cb - 352;        iters = 1; row0 = 0; }

        const float4* base = reinterpret_cast<const float4*>(cp) +
                             (size_t)b * HW + row0 + tid;

        float acc = 0.0f;
        #pragma unroll
        for (int i = 0; i < 8; i++) {
            if (i < iters) {
                const float4 v = base[(size_t)i * 256];
                float m  = fmaxf(fmaxf(v.x, v.y), fmaxf(v.z, v.w));
                float se = __expf(v.x - m) + __expf(v.y - m) +
                           __expf(v.z - m) + __expf(v.w - m);
                acc += (m + __logf(se)) - v.x;     // lse - logit0
            }
        }

        #pragma unroll
        for (int o = 16; o > 0; o >>= 1)
            acc += __shfl_xor_sync(FULL_MASK, acc, o);

        __shared__ float wsum[8];
        int wid = tid >> 5;
        if ((tid & 31) == 0) wsum[wid] = acc;
        __syncthreads();
        if (tid == 0) {
            double s = 0.0;
            #pragma unroll
            for (int i = 0; i < 8; i++) s += (double)wsum[i];
            atomicAdd(&g_S[b], s / (double)HW);
        }
    }

    // ------------------- last-block finalize + reset -------------------
    __shared__ bool is_last;
    __threadfence();
    if (tid == 0) {
        unsigned int v = atomicAdd(&g_arrive, 1u);
        is_last = (v == (unsigned)(TOTAL_BLOCKS - 1));
    }
    __syncthreads();

    if (is_last) {
        __threadfence();   // acquire: see all other blocks' accumulator writes
        if (tid == 0) {
            double cls = g_adj;
            #pragma unroll
            for (int b2 = 0; b2 < BATCH; b2++)
                cls += (double)g_cnt[b2] * g_S[b2];
            float clsf = (float)cls;
            float boxf = (float)g_box;
            float dflf = (float)g_dfl;
            out[0] = 0.3f * clsf + 8.0f * boxf + 1.5f * dflf;
            out[1] = clsf;
            out[2] = boxf;
            out[3] = dflf;
        }
        __syncthreads();   // output computed before anyone resets state
        if (tid < BATCH)     { g_S[tid] = 0.0; g_cnt[tid] = 0; }
        if (tid == BATCH)      g_adj = 0.0;
        if (tid == BATCH + 1)  g_box = 0.0;
        if (tid == BATCH + 2)  g_dfl = 0.0;
        if (tid == BATCH + 3)  g_arrive = 0u;
    }
}

extern "C" void kernel_launch(void* const* d_in, const int* in_sizes, int n_in,
                              void* d_out, int out_size)
{
    // Map inputs by element count (order-agnostic).
    // Unique: reg_p3=33554432, reg_p4=8388608, cls_p5=131072, cls_p6=32768,
    //         targets=10240.
    // Ambiguous pairs resolved by first-occurrence (cls precedes its reg twin
    // in both grouped and interleaved metadata orders):
    //   2097152: first = cls_p3, second = reg_p5
    //   524288 : first = cls_p4, second = reg_p6
    const float *c0 = nullptr, *c1 = nullptr, *c2 = nullptr, *c3 = nullptr;
    const float *r0 = nullptr, *r1 = nullptr, *r2 = nullptr, *r3 = nullptr;
    const float *tg = nullptr;
    int seen2097152 = 0, seen524288 = 0;

    for (int i = 0; i < n_in; i++) {
        const float* p = (const float*)d_in[i];
        switch (in_sizes[i]) {
            case 33554432: r0 = p; break;
            case 8388608:  r1 = p; break;
            case 131072:   c2 = p; break;
            case 32768:    c3 = p; break;
            case 10240:    tg = p; break;
            case 2097152:
                if (seen2097152++ == 0) c0 = p; else r2 = p;
                break;
            case 524288:
                if (seen524288++ == 0) c1 = p; else r3 = p;
                break;
            default: break;
        }
    }

    float* out = (float*)d_out;
    yolo_fused_kernel<<<TOTAL_BLOCKS, 256>>>(c0, c1, c2, c3,
                                             r0, r1, r2, r3, tg, out);
}